// round 2
// baseline (speedup 1.0000x reference)
#include <cuda_runtime.h>
#include <cstdint>

#define B_   128
#define S_   1024
#define I_   128
#define H_   256
#define OFF_SLOPE 0.001f

typedef unsigned long long ull;

// ---------------- packed f32x2 helpers (sm_103a) ----------------
__device__ __forceinline__ ull ffma2(ull a, ull b, ull c) {
    ull d; asm("fma.rn.f32x2 %0, %1, %2, %3;" : "=l"(d) : "l"(a), "l"(b), "l"(c));
    return d;
}
__device__ __forceinline__ ull fadd2(ull a, ull b) {
    ull d; asm("add.rn.f32x2 %0, %1, %2;" : "=l"(d) : "l"(a), "l"(b));
    return d;
}
__device__ __forceinline__ ull pack2(float x, float y) {
    ull d; asm("mov.b64 %0, {%1, %2};" : "=l"(d) : "f"(x), "f"(y));
    return d;
}
__device__ __forceinline__ float2 unpack2(ull v) {
    float2 r; asm("mov.b64 {%0, %1}, %2;" : "=f"(r.x), "=f"(r.y) : "l"(v));
    return r;
}

// ---------------- device scratch (static, no allocations) ----------------
__device__ __align__(16) float g_G[134217728];      // [B*S][1024] = 512 MB
__device__ __align__(16) float g_hbuf[2][B_ * H_];  // double-buffered h exchange
__device__ unsigned g_cnt[16];                      // per-group barrier counters

// ---------------- init: reset counters + h0 = 0 (every launch/replay) ----
__global__ void init_k() {
    unsigned t = blockIdx.x * blockDim.x + threadIdx.x;
    if (t < 16) g_cnt[t] = 0u;
    for (unsigned i = t; i < 2u * B_ * H_; i += gridDim.x * blockDim.x)
        ((float*)g_hbuf)[i] = 0.f;
}

// ---------------- phase A: G = x @ W + bias  (fp32 SGEMM, FFMA2) ---------
// M=131072, K=128, N=1024. Block tile 64(M) x 128(N), BK=32, 256 threads,
// thread tile 8x4; M paired into f32x2 lanes (A pairs free from SMEM layout).
__global__ __launch_bounds__(256) void gemm_xw(const float* __restrict__ X,
                                               const float* __restrict__ Wm,
                                               const float* __restrict__ bias) {
    __shared__ __align__(16) float As[32][68];    // [k][m] transposed, padded
    __shared__ __align__(16) float Bs[32][128];   // [k][n]
    const int m0 = blockIdx.x * 64;
    const int n0 = blockIdx.y * 128;
    const int tid = threadIdx.x;
    const int tx = tid & 31, ty = tid >> 5;

    ull acc2[4][4];   // [m-pair][n]: lanes = (m even, m odd)
#pragma unroll
    for (int mp = 0; mp < 4; mp++)
#pragma unroll
        for (int n = 0; n < 4; n++) acc2[mp][n] = 0ull;

    for (int kt = 0; kt < 128; kt += 32) {
#pragma unroll
        for (int i = 0; i < 2; i++) {
            int lin = tid + i * 256;          // 0..511
            int m = lin >> 3, k4 = lin & 7;
            float4 v = reinterpret_cast<const float4*>(X)[(size_t)(m0 + m) * 32 + (kt >> 2) + k4];
            As[k4 * 4 + 0][m] = v.x; As[k4 * 4 + 1][m] = v.y;
            As[k4 * 4 + 2][m] = v.z; As[k4 * 4 + 3][m] = v.w;
        }
#pragma unroll
        for (int i = 0; i < 4; i++) {
            int lin = tid + i * 256;          // 0..1023
            int k = lin >> 5, n4 = lin & 31;
            reinterpret_cast<float4*>(&Bs[k][0])[n4] =
                reinterpret_cast<const float4*>(Wm)[(size_t)(kt + k) * 256 + (n0 >> 2) + n4];
        }
        __syncthreads();
#pragma unroll
        for (int k = 0; k < 32; k++) {
            float4 b4 = reinterpret_cast<float4*>(&Bs[k][0])[tx];
            ull bd0 = pack2(b4.x, b4.x), bd1 = pack2(b4.y, b4.y);
            ull bd2 = pack2(b4.z, b4.z), bd3 = pack2(b4.w, b4.w);
            const ull* Ap = reinterpret_cast<const ull*>(&As[k][ty * 8]);
            ull a0 = Ap[0], a1 = Ap[1], a2 = Ap[2], a3 = Ap[3];
            acc2[0][0] = ffma2(a0, bd0, acc2[0][0]);
            acc2[0][1] = ffma2(a0, bd1, acc2[0][1]);
            acc2[0][2] = ffma2(a0, bd2, acc2[0][2]);
            acc2[0][3] = ffma2(a0, bd3, acc2[0][3]);
            acc2[1][0] = ffma2(a1, bd0, acc2[1][0]);
            acc2[1][1] = ffma2(a1, bd1, acc2[1][1]);
            acc2[1][2] = ffma2(a1, bd2, acc2[1][2]);
            acc2[1][3] = ffma2(a1, bd3, acc2[1][3]);
            acc2[2][0] = ffma2(a2, bd0, acc2[2][0]);
            acc2[2][1] = ffma2(a2, bd1, acc2[2][1]);
            acc2[2][2] = ffma2(a2, bd2, acc2[2][2]);
            acc2[2][3] = ffma2(a2, bd3, acc2[2][3]);
            acc2[3][0] = ffma2(a3, bd0, acc2[3][0]);
            acc2[3][1] = ffma2(a3, bd1, acc2[3][1]);
            acc2[3][2] = ffma2(a3, bd2, acc2[3][2]);
            acc2[3][3] = ffma2(a3, bd3, acc2[3][3]);
        }
        __syncthreads();
    }
    float4 bv = reinterpret_cast<const float4*>(bias)[(n0 >> 2) + tx];
#pragma unroll
    for (int mp = 0; mp < 4; mp++) {
        float2 p0 = unpack2(acc2[mp][0]), p1 = unpack2(acc2[mp][1]);
        float2 p2 = unpack2(acc2[mp][2]), p3 = unpack2(acc2[mp][3]);
        int m = m0 + ty * 8 + mp * 2;
        float4 o0 = make_float4(p0.x + bv.x, p1.x + bv.y, p2.x + bv.z, p3.x + bv.w);
        float4 o1 = make_float4(p0.y + bv.x, p1.y + bv.y, p2.y + bv.z, p3.y + bv.w);
        reinterpret_cast<float4*>(g_G)[(size_t)m * 256 + (n0 >> 2) + tx] = o0;
        reinterpret_cast<float4*>(g_G)[(size_t)(m + 1) * 256 + (n0 >> 2) + tx] = o1;
    }
}

// ---------------- phase B: persistent recurrent kernel -------------------
__device__ __forceinline__ float sigf(float x) { return 1.0f / (1.0f + __expf(-x)); }

__device__ __forceinline__ unsigned ld_acq(const unsigned* p) {
    unsigned v;
    asm volatile("ld.global.acquire.gpu.u32 %0, [%1];" : "=r"(v) : "l"(p) : "memory");
    return v;
}

// 128 CTAs = 16 groups (8 batches) x 8 h-slices (32 h-units = 128 gate cols).
// U register-resident as packed gate-pairs (i,f)|(g,o). h staged DUPLICATED
// in SMEM so one broadcast LDS.128 yields two f32x2 multiplicands.
__global__ __launch_bounds__(256, 1) void plstm_rec(
    const float* __restrict__ U, const float* __restrict__ ts,
    const float* __restrict__ Per, const float* __restrict__ Shf,
    const float* __restrict__ Oe, float* __restrict__ out, int writeTails) {
    __shared__ __align__(16) float hs_dup[8 * 256 * 2];  // (h,h) pairs, 16 KB
    __shared__ __align__(16) float red[8192];            // partials, 32 KB

    const int tid = threadIdx.x;
    const int grp = blockIdx.x >> 3;
    const int hslc = blockIdx.x & 7;
    const int bg0 = grp * 8;
    const int hs = hslc * 32;
    const int kc = tid >> 5;     // matmul role: K-chunk (= warp id)
    const int jj = tid & 31;     // matmul role: h-unit in slice
    const int ob = kc;           // owner role: batch in group
    const int oj = jj;           // owner role: h-unit in slice
    const int jg = hs + oj;

    const float pv = fabsf(Per[jg]);
    const float sv = Shf[jg];
    const float oe = fabsf(Oe[jg]);
    const float on_end = oe * pv;
    const float on_mid = (oe * 0.5f) * pv;

    // register-resident packed U: Upk[kk][0]=(U_i,U_f), [1]=(U_g,U_o)
    ull Upk[32][2];
    {
        const float* Ub = U + (size_t)(kc * 32) * 1024 + hs + jj;
#pragma unroll
        for (int kk = 0; kk < 32; kk++) {
            float ui = Ub[(size_t)kk * 1024];
            float uf = Ub[(size_t)kk * 1024 + 256];
            float ug = Ub[(size_t)kk * 1024 + 512];
            float uo = Ub[(size_t)kk * 1024 + 768];
            Upk[kk][0] = pack2(ui, uf);
            Upk[kk][1] = pack2(ug, uo);
        }
    }

    float ccar = 0.f, hcar = 0.f;
    const float* tsrow = ts + (size_t)(bg0 + ob) * S_;
    const float* Gbase = g_G + (size_t)(bg0 + ob) * S_ * 1024 + hs + oj;

    for (int s = 0; s < S_; s++) {
        const int cur = s & 1, nxt = cur ^ 1;

        // prefetch owner inputs early (consumed after the FMA block)
        const float* Gp = Gbase + (size_t)s * 1024;
        float Gi = Gp[0], Gf = Gp[256], Gg = Gp[512], Go = Gp[768];
        float tt = tsrow[s];

        // stage h duplicated: (x,x,y,y)(z,z,w,w) per source float4
        {
            const float4* hbp = reinterpret_cast<const float4*>(&g_hbuf[cur][bg0 * H_]);
            float4* hd4 = reinterpret_cast<float4*>(hs_dup);
            float4 v0 = __ldcg(hbp + tid);
            float4 v1 = __ldcg(hbp + tid + 256);
            hd4[2 * tid + 0] = make_float4(v0.x, v0.x, v0.y, v0.y);
            hd4[2 * tid + 1] = make_float4(v0.z, v0.z, v0.w, v0.w);
            hd4[2 * (tid + 256) + 0] = make_float4(v1.x, v1.x, v1.y, v1.y);
            hd4[2 * (tid + 256) + 1] = make_float4(v1.z, v1.z, v1.w, v1.w);
        }
        __syncthreads();

        // matmul partials: 8 batches x (2 packed gate-pairs) x 32 K
        ull acc[8][2];
#pragma unroll
        for (int b = 0; b < 8; b++) { acc[b][0] = 0ull; acc[b][1] = 0ull; }
#pragma unroll
        for (int b = 0; b < 8; b++) {
            const ulonglong2* hp2 = reinterpret_cast<const ulonglong2*>(
                &hs_dup[(b * 256 + kc * 32) * 2]);
#pragma unroll
            for (int k2 = 0; k2 < 16; k2++) {
                ulonglong2 hh = hp2[k2];     // (h_{2k2} dup, h_{2k2+1} dup)
                acc[b][0] = ffma2(hh.x, Upk[2 * k2][0], acc[b][0]);
                acc[b][1] = ffma2(hh.x, Upk[2 * k2][1], acc[b][1]);
                acc[b][0] = ffma2(hh.y, Upk[2 * k2 + 1][0], acc[b][0]);
                acc[b][1] = ffma2(hh.y, Upk[2 * k2 + 1][1], acc[b][1]);
            }
        }

        // write partials, reduce across 8 K-chunks (packed adds)
#pragma unroll
        for (int b = 0; b < 8; b++) {
            ulonglong2 w; w.x = acc[b][0]; w.y = acc[b][1];
            reinterpret_cast<ulonglong2*>(red)[(kc * 8 + b) * 32 + jj] = w;
        }
        __syncthreads();

        ull s01 = 0ull, s23 = 0ull;
#pragma unroll
        for (int q = 0; q < 8; q++) {
            ulonglong2 p = reinterpret_cast<const ulonglong2*>(red)[(q * 8 + ob) * 32 + oj];
            s01 = fadd2(s01, p.x);
            s23 = fadd2(s23, p.y);
        }
        float2 vif = unpack2(s01);
        float2 vgo = unpack2(s23);

        // LSTM cell + phased time gate
        float it = sigf(Gi + vif.x);
        float ft = sigf(Gf + vif.y);
        float gt = tanhf(Gg + vgo.x);
        float ot = sigf(Go + vgo.y);
        float cn = ft * ccar + it * gt;
        float hn = ot * tanhf(cn);

        float ic = fmodf(tt + sv, pv);
        float mask;
        if (ic <= on_mid)      mask = ic / on_mid;
        else if (ic <= on_end) mask = (on_end - ic) / on_mid;
        else                   mask = OFF_SLOPE * (ic / pv);

        ccar = mask * cn + (1.f - mask) * ccar;
        float h2 = mask * hn + (1.f - mask) * hcar;
        hcar = h2;

        out[((size_t)(bg0 + ob) * S_ + s) * H_ + jg] = h2;
        g_hbuf[nxt][(bg0 + ob) * H_ + jg] = h2;

        // group barrier (8 CTAs, monotonic counter)
        __syncthreads();
        if (tid == 0) {
            __threadfence();
            atomicAdd(&g_cnt[grp], 1u);
            const unsigned tgt = 8u * (unsigned)(s + 1);
            while (ld_acq(&g_cnt[grp]) < tgt) {}
        }
        __syncthreads();
    }

    if (writeTails) {
        const size_t baseT = (size_t)B_ * S_ * H_;
        out[baseT + (size_t)(bg0 + ob) * H_ + jg] = hcar;                    // h_T
        out[baseT + (size_t)B_ * H_ + (size_t)(bg0 + ob) * H_ + jg] = ccar;  // c_T
    }
}

// ---------------- launch ----------------
extern "C" void kernel_launch(void* const* d_in, const int* in_sizes, int n_in,
                              void* d_out, int out_size) {
    const float* x    = (const float*)d_in[0];
    const float* ts   = (const float*)d_in[1];
    const float* W    = (const float*)d_in[2];
    const float* U    = (const float*)d_in[3];
    const float* bias = (const float*)d_in[4];
    const float* Per  = (const float*)d_in[5];
    const float* Shf  = (const float*)d_in[6];
    const float* Oe   = (const float*)d_in[7];
    float* out = (float*)d_out;

    init_k<<<64, 256>>>();

    dim3 gg(131072 / 64, 1024 / 128);
    gemm_xw<<<gg, 256>>>(x, W, bias);

    const long long need = (long long)B_ * S_ * H_ + 2LL * B_ * H_;
    int writeTails = ((long long)out_size >= need) ? 1 : 0;
    plstm_rec<<<128, 256>>>(U, ts, Per, Shf, Oe, out, writeTails);
}